// round 11
// baseline (speedup 1.0000x reference)
#include <cuda_runtime.h>
#include <math.h>

#define NLEV 3
#define NBMAX 16
#define MAXB 64
#define NCLS 80
#define PMAX 1024
// main blocks per image-level over 3*HW cells, 256 threads (scalar)
#define LB0 32
#define LB1 8
#define LB2 2
#define LBPI (LB0 + LB1 + LB2)   // 42 -> N=16 => 672 main blocks
#define PBLK 18                  // positive-path blocks (144 warps)

__constant__ float c_stride[NLEV] = {8.f, 16.f, 32.f};
__constant__ float c_anchor[NLEV][3][2] = {
    {{12.f, 16.f}, {19.f, 36.f}, {40.f, 28.f}},
    {{36.f, 75.f}, {76.f, 55.f}, {72.f, 146.f}},
    {{142.f, 110.f}, {192.f, 243.f}, {459.f, 401.f}}
};

// Persistent scratch; statically zero-initialized; finalize resets all.
__device__ float4   g_boxes[NLEV][NBMAX][MAXB];   // corners x1,y1,x2,y2
__device__ float    g_area [NLEV][NBMAX][MAXB];   // ta/3
__device__ int      g_key  [NLEV][NBMAX][MAXB];   // cell key = a*HW + hw
__device__ int      g_count[NLEV][NBMAX];
__device__ unsigned g_grp  [NLEV][NBMAX];         // group barrier counters
__device__ unsigned g_plist[PMAX];                // packed (lev<<17 | n<<13 | key)
__device__ int      g_pcount;
__device__ unsigned g_gdone;                      // main blocks done gathering
__device__ double   g_acc[3];
__device__ unsigned g_done;

__device__ __forceinline__ float bce_logits(float x, float t) {
    return fmaxf(x, 0.f) - x * t + __logf(1.f + __expf(-fabsf(x)));
}

__global__ void __launch_bounds__(256, 6)
k_yolo(const float* __restrict__ f0, const float* __restrict__ f1,
       const float* __restrict__ f2,
       const float* __restrict__ lab0, const float* __restrict__ lab1,
       const float* __restrict__ lab2,
       int N, float* __restrict__ out) {
    const int b = blockIdx.x;
    const int nMain = N * LBPI;
    const int warp = threadIdx.x >> 5, lane = threadIdx.x & 31;

    float r_reg = 0.f, r_conf = 0.f, r_prob = 0.f;

    if (b < nMain) {
        // ================= main block: gather + conf loss (scalar) =================
        const int n = b / LBPI;
        const int r = b - n * LBPI;
        int lev, chunk, H, gs;
        const float* feat; const float* label;
        if (r < LB0)            { lev = 0; chunk = r;             H = 52; feat = f0; label = lab0; gs = LB0; }
        else if (r < LB0 + LB1) { lev = 1; chunk = r - LB0;       H = 26; feat = f1; label = lab1; gs = LB1; }
        else                    { lev = 2; chunk = r - LB0 - LB1; H = 13; feat = f2; label = lab2; gs = LB2; }
        const int W = H, HW = H * W;
        const int C3 = 3 * HW;

        const int idx = chunk * 256 + threadIdx.x;   // a*HW + hw (feature order)
        const bool act = idx < C3;

        // ---- issue conf (strided) + 5 feature loads in one window ----
        int a = 0, hw = 0;
        float lc = 0.f, rx = 0.f, ry = 0.f, rw = 0.f, rh = 0.f, rc = 0.f;
        size_t lb = 0;
        if (act) {
            a  = idx / HW;
            hw = idx - a * HW;
            lb = ((size_t)(n * HW + hw) * 3 + a) * 85;
            lc = __ldg(label + lb + 4);                       // longest latency: first
            const float* fb = feat + ((size_t)(n * 255 + a * 85)) * HW + hw;
            rx = fb[0];
            ry = fb[(size_t)HW];
            rw = fb[(size_t)2 * HW];
            rh = fb[(size_t)3 * HW];
            rc = fb[(size_t)4 * HW];

            if (lc > 0.f) {                                   // rare (~0.08%)
                const float x = __ldg(label + lb + 0);
                const float y = __ldg(label + lb + 1);
                const float w = __ldg(label + lb + 2);
                const float h = __ldg(label + lb + 3);
                const int slot = atomicAdd(&g_count[lev][n], 1);
                if (slot < MAXB) {
                    g_boxes[lev][n][slot] = make_float4(x - 0.5f * w, y - 0.5f * h,
                                                        x + 0.5f * w, y + 0.5f * h);
                    g_area[lev][n][slot] = w * h * (1.f / 3.f);
                    g_key [lev][n][slot] = idx;
                }
                const int ps = atomicAdd(&g_pcount, 1);
                if (ps < PMAX)
                    g_plist[ps] = ((unsigned)lev << 17) | ((unsigned)n << 13) | (unsigned)idx;
            }
        }

        // ---- group barrier (32/8/2 blocks) + global gather-done signal ----
        __threadfence();
        __syncthreads();
        if (threadIdx.x == 0) {
            atomicAdd(&g_gdone, 1u);
            atomicAdd(&g_grp[lev][n], 1u);
            volatile unsigned* p = &g_grp[lev][n];
            while (*p < (unsigned)gs) { __nanosleep(32); }
            __threadfence();
        }
        __syncthreads();

        // ---- stage boxes ----
        __shared__ float4 s_box[MAXB];
        __shared__ float  s_ta3[MAXB];
        __shared__ int    s_key[MAXB];
        const int cnt = min(g_count[lev][n], MAXB);
        if (threadIdx.x < cnt) {
            s_box[threadIdx.x] = g_boxes[lev][n][threadIdx.x];
            s_ta3[threadIdx.x] = g_area[lev][n][threadIdx.x];
            s_key[threadIdx.x] = g_key[lev][n][threadIdx.x];
        }
        __syncthreads();

        // ---- conf loss ----
        if (act) {
            bool pos = false, ignore = true;
            if (cnt > 0) {
                const float gx = (float)(hw % W);
                const float gy = (float)(hw / W);
                const float stride = c_stride[lev];
                // merged sigmoid pair: one rcp for both x and y
                const float ex = __expf(-rx), ey = __expf(-ry);
                const float d  = __fdividef(1.f, (1.f + ex) * (1.f + ey));
                const float px = ((1.f + ey) * d + gx) * stride;
                const float py = ((1.f + ex) * d + gy) * stride;
                const float pw = __expf(rw) * c_anchor[lev][a][0];
                const float ph = __expf(rh) * c_anchor[lev][a][1];
                const float px1 = px - 0.5f * pw, py1 = py - 0.5f * ph;
                const float px2 = px + 0.5f * pw, py2 = py + 0.5f * ph;
                const float pa3 = pw * ph * (1.f / 3.f);
                // iou >= 0.5  <=>  inter >= pa/3 + ta/3   (pa,ta > 0)
                #pragma unroll 4
                for (int k = 0; k < cnt; k++) {
                    const float4 t = s_box[k];
                    const float iw = fmaxf(fminf(px2, t.z) - fmaxf(px1, t.x), 0.f);
                    const float ih = fmaxf(fminf(py2, t.w) - fmaxf(py1, t.y), 0.f);
                    if (iw * ih >= pa3 + s_ta3[k]) ignore = false;
                    if (s_key[k] == idx) pos = true;
                }
            }
            const float bc = bce_logits(rc, pos ? 1.f : 0.f);
            r_conf = pos ? bc : (ignore ? bc : 0.f);
        }
    } else {
        // ================= positive path: warp-per-positive =================
        if (threadIdx.x == 0) {
            volatile unsigned* p = &g_gdone;
            while (*p < (unsigned)nMain) { __nanosleep(64); }
            __threadfence();
        }
        __syncthreads();

        const int pcount = min(g_pcount, PMAX);
        const int gw = (b - nMain) * 8 + warp;
        for (int p = gw; p < pcount; p += PBLK * 8) {
            const unsigned pk = g_plist[p];
            const int lev = (int)(pk >> 17);
            const int n   = (int)((pk >> 13) & 15u);
            const int key = (int)(pk & 0x1FFFu);
            int H; const float* feat; const float* label;
            if (lev == 0)      { H = 52; feat = f0; label = lab0; }
            else if (lev == 1) { H = 26; feat = f1; label = lab1; }
            else               { H = 13; feat = f2; label = lab2; }
            const int W = H, HW = H * W;
            const int a  = key / HW;
            const int hw = key - a * HW;

            const float* fb = feat + ((size_t)(n * 255 + a * 85)) * HW + hw;
            const float* Lb = label + ((size_t)(n * HW + hw) * 3 + a) * 85;

            float fv = 0.f, lv = 0.f;
            if (lane < 4) {
                fv = fb[(size_t)lane * HW];
                lv = __ldg(Lb + lane);
            }
            const float rx = __shfl_sync(0xffffffffu, fv, 0);
            const float ry = __shfl_sync(0xffffffffu, fv, 1);
            const float rw = __shfl_sync(0xffffffffu, fv, 2);
            const float rh = __shfl_sync(0xffffffffu, fv, 3);
            const float lx = __shfl_sync(0xffffffffu, lv, 0);
            const float ly = __shfl_sync(0xffffffffu, lv, 1);
            const float lw = __shfl_sync(0xffffffffu, lv, 2);
            const float lh = __shfl_sync(0xffffffffu, lv, 3);

            float ps = 0.f;
            #pragma unroll
            for (int c0 = 0; c0 < NCLS; c0 += 32) {
                const int c = c0 + lane;
                if (c < NCLS) {
                    const float rp = fb[(size_t)(5 + c) * HW];
                    const float lp = __ldg(Lb + 5 + c);
                    ps += bce_logits(rp, lp);
                }
            }
            r_prob += ps;

            if (lane == 0) {
                const float gx = (float)(hw % W);
                const float gy = (float)(hw / W);
                const float stride = c_stride[lev];
                const float aw = c_anchor[lev][a][0];
                const float ah = c_anchor[lev][a][1];
                const float scale = 2.f - lw * lh * (1.f / (416.f * 416.f));
                const float inv_s = __fdividef(1.f, stride);
                const float ox = lx * inv_s - gx;
                const float oy = ly * inv_s - gy;
                const float xy = bce_logits(rx, ox) + bce_logits(ry, oy);
                const float wx = __logf(__fdividef(lw, aw) + 1e-7f);
                const float wy = __logf(__fdividef(lh, ah) + 1e-7f);
                const float dwx = rw - wx, dwy = rh - wy;
                r_reg += scale * (xy + 0.5f * (dwx * dwx + dwy * dwy));
            }
        }
    }

    // ---- block reduction + last-block finalize ----
    #pragma unroll
    for (int o = 16; o; o >>= 1) {
        r_reg  += __shfl_xor_sync(0xffffffffu, r_reg,  o);
        r_conf += __shfl_xor_sync(0xffffffffu, r_conf, o);
        r_prob += __shfl_xor_sync(0xffffffffu, r_prob, o);
    }
    __shared__ float s_r[8], s_c[8], s_p[8];
    if (lane == 0) { s_r[warp] = r_reg; s_c[warp] = r_conf; s_p[warp] = r_prob; }
    __syncthreads();

    if (threadIdx.x == 0) {
        float R = 0.f, C = 0.f, P = 0.f;
        #pragma unroll
        for (int w = 0; w < 8; w++) { R += s_r[w]; C += s_c[w]; P += s_p[w]; }
        atomicAdd(&g_acc[0], (double)R);
        atomicAdd(&g_acc[1], (double)C);
        atomicAdd(&g_acc[2], (double)P);

        __threadfence();
        const unsigned t = atomicAdd(&g_done, 1u);
        if (t == (unsigned)gridDim.x - 1u) {
            const double v0 = atomicAdd(&g_acc[0], 0.0);
            const double v1 = atomicAdd(&g_acc[1], 0.0);
            const double v2 = atomicAdd(&g_acc[2], 0.0);
            const double invN = 1.0 / (double)N;
            out[0] = (float)(v0 * invN);
            out[1] = (float)(v1 * invN);
            out[2] = (float)(v2 * invN);
            g_acc[0] = 0.0; g_acc[1] = 0.0; g_acc[2] = 0.0;
            #pragma unroll
            for (int l = 0; l < NLEV; l++)
                #pragma unroll
                for (int m = 0; m < NBMAX; m++) { g_count[l][m] = 0; g_grp[l][m] = 0u; }
            g_pcount = 0;
            g_gdone = 0u;
            g_done = 0u;
            __threadfence();
        }
    }
}

extern "C" void kernel_launch(void* const* d_in, const int* in_sizes, int n_in,
                              void* d_out, int out_size) {
    const float* f0 = (const float*)d_in[0];
    const float* f1 = (const float*)d_in[1];
    const float* f2 = (const float*)d_in[2];
    const float* l0 = (const float*)d_in[3];
    const float* l1 = (const float*)d_in[4];
    const float* l2 = (const float*)d_in[5];

    int N = in_sizes[0] / (255 * 52 * 52);
    if (N > NBMAX) N = NBMAX;

    k_yolo<<<N * LBPI + PBLK, 256>>>(f0, f1, f2, l0, l1, l2, N, (float*)d_out);
}

// round 12
// speedup vs baseline: 1.1379x; 1.1379x over previous
#include <cuda_runtime.h>
#include <math.h>

#define NLEV 3
#define NBMAX 16
#define MAXB 64
#define NCLS 80
#define PMAX 1024
// cells per image per level (3*HW)
#define CPI0 8112
#define CPI1 2028
#define CPI2 507
#define CPI_ALL 10647
// gather blocks (scheduled first)
#define GBLK 96
// main loss blocks per image: lev0 pairs 4056 -> 16, lev1 pairs 1014 -> 4, lev2 scalar 507 -> 2
#define VB0 16
#define VB1 4
#define SB2 2
#define LBPI (VB0 + VB1 + SB2)   // 22 -> N=16 => 352 main blocks
#define PBLK 18                  // positive-path blocks

__constant__ float c_stride[NLEV] = {8.f, 16.f, 32.f};
__constant__ float c_anchor[NLEV][3][2] = {
    {{12.f, 16.f}, {19.f, 36.f}, {40.f, 28.f}},
    {{36.f, 75.f}, {76.f, 55.f}, {72.f, 146.f}},
    {{142.f, 110.f}, {192.f, 243.f}, {459.f, 401.f}}
};

// Persistent scratch; statically zero-initialized; finalize resets all.
__device__ float4   g_boxes[NLEV][NBMAX][MAXB];   // corners x1,y1,x2,y2
__device__ float    g_area [NLEV][NBMAX][MAXB];   // ta/3
__device__ int      g_key  [NLEV][NBMAX][MAXB];   // cell key = a*HW + hw
__device__ int      g_count[NLEV][NBMAX];
__device__ unsigned g_plist[PMAX];                // packed (lev<<17 | n<<13 | key)
__device__ int      g_pcount;
__device__ unsigned g_gready;                     // gather blocks completed
__device__ double   g_acc[3];
__device__ unsigned g_done;

__device__ __forceinline__ float bce_logits(float x, float t) {
    return fmaxf(x, 0.f) - x * t + __logf(1.f + __expf(-fabsf(x)));
}

__global__ void __launch_bounds__(256, 4)
k_yolo(const float* __restrict__ f0, const float* __restrict__ f1,
       const float* __restrict__ f2,
       const float* __restrict__ lab0, const float* __restrict__ lab1,
       const float* __restrict__ lab2,
       int N, float* __restrict__ out) {
    const int b = blockIdx.x;
    const int warp = threadIdx.x >> 5, lane = threadIdx.x & 31;

    float r_reg = 0.f, r_conf = 0.f, r_prob = 0.f;

    if (b < GBLK) {
        // ================= gather blocks: strided conf scan, MLP=7 =================
        const int total = N * CPI_ALL;                       // 170352 for N=16
        const int cA = N * CPI0, cB = N * CPI1;
        const int base = b * 256 + threadIdx.x;
        const int step = GBLK * 256;                         // 24576

        const float* P[7];
        bool ok[7];
        #pragma unroll
        for (int r = 0; r < 7; r++) {
            const int i = base + r * step;
            ok[r] = i < total;
            int j; const float* L;
            if (i < cA)           { j = i;           L = lab0; }
            else if (i < cA + cB) { j = i - cA;      L = lab1; }
            else                  { j = i - cA - cB; L = lab2; }
            P[r] = (ok[r] ? L : lab0) + (size_t)(ok[r] ? j : 0) * 85;
        }
        float conf[7];
        #pragma unroll
        for (int r = 0; r < 7; r++) conf[r] = __ldg(P[r] + 4);   // 7 loads in flight

        #pragma unroll
        for (int r = 0; r < 7; r++) {
            if (ok[r] && conf[r] > 0.f) {                    // rare (~0.08%)
                const int i = base + r * step;
                int lev, j, HW;
                if (i < cA)           { lev = 0; j = i;           HW = 2704; }
                else if (i < cA + cB) { lev = 1; j = i - cA;      HW = 676;  }
                else                  { lev = 2; j = i - cA - cB; HW = 169;  }
                const int n   = j / (3 * HW);
                const int rem = j - n * 3 * HW;
                const int hw  = rem / 3;
                const int a   = rem - hw * 3;
                const int key = a * HW + hw;
                const float x = __ldg(P[r] + 0), y = __ldg(P[r] + 1);
                const float w = __ldg(P[r] + 2), h = __ldg(P[r] + 3);
                const int slot = atomicAdd(&g_count[lev][n], 1);
                if (slot < MAXB) {
                    g_boxes[lev][n][slot] = make_float4(x - 0.5f * w, y - 0.5f * h,
                                                        x + 0.5f * w, y + 0.5f * h);
                    g_area[lev][n][slot] = w * h * (1.f / 3.f);
                    g_key [lev][n][slot] = key;
                }
                const int ps = atomicAdd(&g_pcount, 1);
                if (ps < PMAX)
                    g_plist[ps] = ((unsigned)lev << 17) | ((unsigned)n << 13) | (unsigned)key;
            }
        }
        __threadfence();
        __syncthreads();
        if (threadIdx.x == 0) atomicAdd(&g_gready, 1u);
    } else if (b < GBLK + N * LBPI) {
        // ================= main blocks: features (vec2) + conf loss =================
        const int mb = b - GBLK;
        const int n = mb / LBPI;
        const int r = mb - n * LBPI;
        int lev, chunk, H;
        const float* feat;
        bool vec;
        if (r < VB0)            { lev = 0; chunk = r;             H = 52; feat = f0; vec = true; }
        else if (r < VB0 + VB1) { lev = 1; chunk = r - VB0;       H = 26; feat = f1; vec = true; }
        else                    { lev = 2; chunk = r - VB0 - VB1; H = 13; feat = f2; vec = false; }
        const int W = H, HW = H * W;
        const int C3 = 3 * HW;

        // ---- issue coalesced feature loads FIRST (overlap with gather wait) ----
        int idx0 = 0, a = 0, hw0 = 0;
        float2 rx2 = {0.f,0.f}, ry2 = {0.f,0.f}, rw2 = {0.f,0.f},
               rh2 = {0.f,0.f}, rc2 = {0.f,0.f};
        bool act;
        if (vec) {
            const int pair = chunk * 256 + threadIdx.x;
            act = pair < (C3 >> 1);
            if (act) {
                idx0 = pair * 2;
                a = idx0 / HW; hw0 = idx0 - a * HW;
                const float* fb = feat + ((size_t)(n * 255 + a * 85)) * HW + hw0;
                rx2 = *reinterpret_cast<const float2*>(fb);
                ry2 = *reinterpret_cast<const float2*>(fb + (size_t)HW);
                rw2 = *reinterpret_cast<const float2*>(fb + (size_t)2 * HW);
                rh2 = *reinterpret_cast<const float2*>(fb + (size_t)3 * HW);
                rc2 = *reinterpret_cast<const float2*>(fb + (size_t)4 * HW);
            }
        } else {
            const int idx = chunk * 256 + threadIdx.x;
            act = idx < C3;
            if (act) {
                idx0 = idx;
                a = idx / HW; hw0 = idx - a * HW;
                const float* fb = feat + ((size_t)(n * 255 + a * 85)) * HW + hw0;
                rx2.x = fb[0];
                ry2.x = fb[(size_t)HW];
                rw2.x = fb[(size_t)2 * HW];
                rh2.x = fb[(size_t)3 * HW];
                rc2.x = fb[(size_t)4 * HW];
            }
        }

        // ---- wait for all gather blocks (overlapped with in-flight loads) ----
        if (threadIdx.x == 0) {
            volatile unsigned* p = &g_gready;
            while (*p < (unsigned)GBLK) { __nanosleep(32); }
            __threadfence();
        }
        __syncthreads();

        // ---- stage boxes ----
        __shared__ float4 s_box[MAXB];
        __shared__ float  s_ta3[MAXB];
        __shared__ int    s_key[MAXB];
        const int cnt = min(g_count[lev][n], MAXB);
        if (threadIdx.x < cnt) {
            s_box[threadIdx.x] = g_boxes[lev][n][threadIdx.x];
            s_ta3[threadIdx.x] = g_area[lev][n][threadIdx.x];
            s_key[threadIdx.x] = g_key[lev][n][threadIdx.x];
        }
        __syncthreads();

        // ---- conf loss ----
        if (act) {
            const float gy  = (float)(hw0 / W);
            const float gx0 = (float)(hw0 - (hw0 / W) * W);
            const float stride = c_stride[lev];
            const float aw = c_anchor[lev][a][0];
            const float ah = c_anchor[lev][a][1];

            bool pos0 = false, pos1 = false, ign0 = true, ign1 = true;
            const int nCell = vec ? 2 : 1;
            if (cnt > 0) {
                const float ex0 = __expf(-rx2.x), ey0 = __expf(-ry2.x);
                const float d0  = __fdividef(1.f, (1.f + ex0) * (1.f + ey0));
                const float px0 = ((1.f + ey0) * d0 + gx0) * stride;
                const float py0 = ((1.f + ex0) * d0 + gy)  * stride;
                const float pw0 = __expf(rw2.x) * aw, ph0 = __expf(rh2.x) * ah;
                const float ax1 = px0 - 0.5f * pw0, ay1 = py0 - 0.5f * ph0;
                const float ax2 = px0 + 0.5f * pw0, ay2 = py0 + 0.5f * ph0;
                const float pa3a = pw0 * ph0 * (1.f / 3.f);
                float bx1 = 0.f, by1 = 0.f, bx2 = 0.f, by2 = 0.f, pa3b = 0.f;
                if (nCell == 2) {
                    const float ex1 = __expf(-rx2.y), ey1 = __expf(-ry2.y);
                    const float d1  = __fdividef(1.f, (1.f + ex1) * (1.f + ey1));
                    const float px1c = ((1.f + ey1) * d1 + gx0 + 1.f) * stride;
                    const float py1c = ((1.f + ex1) * d1 + gy) * stride;
                    const float pw1 = __expf(rw2.y) * aw, ph1 = __expf(rh2.y) * ah;
                    bx1 = px1c - 0.5f * pw1; by1 = py1c - 0.5f * ph1;
                    bx2 = px1c + 0.5f * pw1; by2 = py1c + 0.5f * ph1;
                    pa3b = pw1 * ph1 * (1.f / 3.f);
                }
                // iou >= 0.5  <=>  inter >= pa/3 + ta/3   (pa,ta > 0)
                #pragma unroll 2
                for (int k = 0; k < cnt; k++) {
                    const float4 t = s_box[k];
                    const float ta3 = s_ta3[k];
                    const int   key = s_key[k];
                    {
                        const float iw = fmaxf(fminf(ax2, t.z) - fmaxf(ax1, t.x), 0.f);
                        const float ih = fmaxf(fminf(ay2, t.w) - fmaxf(ay1, t.y), 0.f);
                        if (iw * ih >= pa3a + ta3) ign0 = false;
                        if (key == idx0) pos0 = true;
                    }
                    if (nCell == 2) {
                        const float iw = fmaxf(fminf(bx2, t.z) - fmaxf(bx1, t.x), 0.f);
                        const float ih = fmaxf(fminf(by2, t.w) - fmaxf(by1, t.y), 0.f);
                        if (iw * ih >= pa3b + ta3) ign1 = false;
                        if (key == idx0 + 1) pos1 = true;
                    }
                }
            }
            {
                const float bc = bce_logits(rc2.x, pos0 ? 1.f : 0.f);
                r_conf += pos0 ? bc : (ign0 ? bc : 0.f);
            }
            if (nCell == 2) {
                const float bc = bce_logits(rc2.y, pos1 ? 1.f : 0.f);
                r_conf += pos1 ? bc : (ign1 ? bc : 0.f);
            }
        }
    } else {
        // ================= positive path: warp-per-positive =================
        if (threadIdx.x == 0) {
            volatile unsigned* p = &g_gready;
            while (*p < (unsigned)GBLK) { __nanosleep(64); }
            __threadfence();
        }
        __syncthreads();

        const int pcount = min(g_pcount, PMAX);
        const int gw = (b - GBLK - N * LBPI) * 8 + warp;
        for (int p = gw; p < pcount; p += PBLK * 8) {
            const unsigned pk = g_plist[p];
            const int lev = (int)(pk >> 17);
            const int n   = (int)((pk >> 13) & 15u);
            const int key = (int)(pk & 0x1FFFu);
            int H; const float* feat; const float* label;
            if (lev == 0)      { H = 52; feat = f0; label = lab0; }
            else if (lev == 1) { H = 26; feat = f1; label = lab1; }
            else               { H = 13; feat = f2; label = lab2; }
            const int W = H, HW = H * W;
            const int a  = key / HW;
            const int hw = key - a * HW;

            const float* fb = feat + ((size_t)(n * 255 + a * 85)) * HW + hw;
            const float* Lb = label + ((size_t)(n * HW + hw) * 3 + a) * 85;

            float fv = 0.f, lv = 0.f;
            if (lane < 4) {
                fv = fb[(size_t)lane * HW];
                lv = __ldg(Lb + lane);
            }
            const float rx = __shfl_sync(0xffffffffu, fv, 0);
            const float ry = __shfl_sync(0xffffffffu, fv, 1);
            const float rw = __shfl_sync(0xffffffffu, fv, 2);
            const float rh = __shfl_sync(0xffffffffu, fv, 3);
            const float lx = __shfl_sync(0xffffffffu, lv, 0);
            const float ly = __shfl_sync(0xffffffffu, lv, 1);
            const float lw = __shfl_sync(0xffffffffu, lv, 2);
            const float lh = __shfl_sync(0xffffffffu, lv, 3);

            float ps = 0.f;
            #pragma unroll
            for (int c0 = 0; c0 < NCLS; c0 += 32) {
                const int c = c0 + lane;
                if (c < NCLS) {
                    const float rp = fb[(size_t)(5 + c) * HW];
                    const float lp = __ldg(Lb + 5 + c);
                    ps += bce_logits(rp, lp);
                }
            }
            r_prob += ps;

            if (lane == 0) {
                const float gx = (float)(hw % W);
                const float gy = (float)(hw / W);
                const float stride = c_stride[lev];
                const float aw = c_anchor[lev][a][0];
                const float ah = c_anchor[lev][a][1];
                const float scale = 2.f - lw * lh * (1.f / (416.f * 416.f));
                const float inv_s = __fdividef(1.f, stride);
                const float ox = lx * inv_s - gx;
                const float oy = ly * inv_s - gy;
                const float xy = bce_logits(rx, ox) + bce_logits(ry, oy);
                const float wx = __logf(__fdividef(lw, aw) + 1e-7f);
                const float wy = __logf(__fdividef(lh, ah) + 1e-7f);
                const float dwx = rw - wx, dwy = rh - wy;
                r_reg += scale * (xy + 0.5f * (dwx * dwx + dwy * dwy));
            }
        }
    }

    // ---- block reduction + last-block finalize ----
    #pragma unroll
    for (int o = 16; o; o >>= 1) {
        r_reg  += __shfl_xor_sync(0xffffffffu, r_reg,  o);
        r_conf += __shfl_xor_sync(0xffffffffu, r_conf, o);
        r_prob += __shfl_xor_sync(0xffffffffu, r_prob, o);
    }
    __shared__ float s_r[8], s_c[8], s_p[8];
    if (lane == 0) { s_r[warp] = r_reg; s_c[warp] = r_conf; s_p[warp] = r_prob; }
    __syncthreads();

    if (threadIdx.x == 0) {
        float R = 0.f, C = 0.f, P = 0.f;
        #pragma unroll
        for (int w = 0; w < 8; w++) { R += s_r[w]; C += s_c[w]; P += s_p[w]; }
        atomicAdd(&g_acc[0], (double)R);
        atomicAdd(&g_acc[1], (double)C);
        atomicAdd(&g_acc[2], (double)P);

        __threadfence();
        const unsigned t = atomicAdd(&g_done, 1u);
        if (t == (unsigned)gridDim.x - 1u) {
            const double v0 = atomicAdd(&g_acc[0], 0.0);
            const double v1 = atomicAdd(&g_acc[1], 0.0);
            const double v2 = atomicAdd(&g_acc[2], 0.0);
            const double invN = 1.0 / (double)N;
            out[0] = (float)(v0 * invN);
            out[1] = (float)(v1 * invN);
            out[2] = (float)(v2 * invN);
            g_acc[0] = 0.0; g_acc[1] = 0.0; g_acc[2] = 0.0;
            #pragma unroll
            for (int l = 0; l < NLEV; l++)
                #pragma unroll
                for (int m = 0; m < NBMAX; m++) g_count[l][m] = 0;
            g_pcount = 0;
            g_gready = 0u;
            g_done = 0u;
            __threadfence();
        }
    }
}

extern "C" void kernel_launch(void* const* d_in, const int* in_sizes, int n_in,
                              void* d_out, int out_size) {
    const float* f0 = (const float*)d_in[0];
    const float* f1 = (const float*)d_in[1];
    const float* f2 = (const float*)d_in[2];
    const float* l0 = (const float*)d_in[3];
    const float* l1 = (const float*)d_in[4];
    const float* l2 = (const float*)d_in[5];

    int N = in_sizes[0] / (255 * 52 * 52);
    if (N > NBMAX) N = NBMAX;

    k_yolo<<<GBLK + N * LBPI + PBLK, 256>>>(f0, f1, f2, l0, l1, l2, N, (float*)d_out);
}

// round 13
// speedup vs baseline: 1.1404x; 1.0022x over previous
#include <cuda_runtime.h>
#include <math.h>

#define NLEV 3
#define NBMAX 16
#define MAXB 64
#define NCLS 80
#define PMAX 1024
// main loss blocks per image: lev0 pairs 4056 -> 16, lev1 pairs 1014 -> 4, lev2 scalar 507 -> 2
#define VB0 16
#define VB1 4
#define SB2 2
#define LBPI (VB0 + VB1 + SB2)   // 22 -> N=16 => 352 main blocks
#define PBLK 18                  // positive-path blocks

__constant__ float c_stride[NLEV] = {8.f, 16.f, 32.f};
__constant__ float c_anchor[NLEV][3][2] = {
    {{12.f, 16.f}, {19.f, 36.f}, {40.f, 28.f}},
    {{36.f, 75.f}, {76.f, 55.f}, {72.f, 146.f}},
    {{142.f, 110.f}, {192.f, 243.f}, {459.f, 401.f}}
};

// Persistent scratch; statically zero-initialized; finalize resets all.
__device__ float4   g_boxes[NLEV][NBMAX][MAXB];   // corners x1,y1,x2,y2
__device__ float    g_area [NLEV][NBMAX][MAXB];   // ta/3
__device__ int      g_key  [NLEV][NBMAX][MAXB];   // cell key = a*HW + hw
__device__ int      g_count[NLEV][NBMAX];
__device__ unsigned g_grp  [NLEV][NBMAX];         // warp-granular arrival counters
__device__ unsigned g_plist[PMAX];                // packed (lev<<17 | n<<13 | key)
__device__ int      g_pcount;
__device__ unsigned g_gdone;                      // main warps done gathering
__device__ double   g_acc[3];
__device__ unsigned g_done;

__device__ __forceinline__ float bce0(float x) {  // bce(x, 0); bce(x,1) = bce0(x) - x
    return fmaxf(x, 0.f) + __logf(1.f + __expf(-fabsf(x)));
}
__device__ __forceinline__ float bce_logits(float x, float t) {
    return fmaxf(x, 0.f) - x * t + __logf(1.f + __expf(-fabsf(x)));
}

__global__ void __launch_bounds__(256, 4)
k_yolo(const float* __restrict__ f0, const float* __restrict__ f1,
       const float* __restrict__ f2,
       const float* __restrict__ lab0, const float* __restrict__ lab1,
       const float* __restrict__ lab2,
       int N, float* __restrict__ out) {
    const int b = blockIdx.x;
    const int nMain = N * LBPI;
    const int warp = threadIdx.x >> 5, lane = threadIdx.x & 31;

    float r_reg = 0.f, r_conf = 0.f, r_prob = 0.f;

    if (b < nMain) {
        // ================= main block =================
        const int n = b / LBPI;
        const int r = b - n * LBPI;
        int lev, chunk, H, gs;
        const float* feat; const float* label;
        bool vec;
        if (r < VB0)            { lev = 0; chunk = r;             H = 52; feat = f0; label = lab0; gs = VB0; vec = true; }
        else if (r < VB0 + VB1) { lev = 1; chunk = r - VB0;       H = 26; feat = f1; label = lab1; gs = VB1; vec = true; }
        else                    { lev = 2; chunk = r - VB0 - VB1; H = 13; feat = f2; label = lab2; gs = SB2; vec = false; }
        const int W = H, HW = H * W;
        const int C3 = 3 * HW;

        // ---- issue gather conf loads + feature loads in one window ----
        const int K = vec ? 2 : 1;
        const int cbase = chunk * 256 + threadIdx.x;
        const int cstep = gs * 256;
        float cf[2];
        #pragma unroll
        for (int k = 0; k < 2; k++) {
            const int c = cbase + k * cstep;
            const bool v = (k < K) && (c < C3);
            cf[k] = v ? __ldg(label + (size_t)(n * C3 + (v ? c : 0)) * 85 + 4) : 0.f;
        }

        int idx0 = 0, a = 0, hw0 = 0;
        float2 rx2 = {0.f,0.f}, ry2 = {0.f,0.f}, rw2 = {0.f,0.f},
               rh2 = {0.f,0.f}, rc2 = {0.f,0.f};
        bool act;
        if (vec) {
            const int pair = chunk * 256 + threadIdx.x;
            act = pair < (C3 >> 1);
            if (act) {
                idx0 = pair * 2;
                a = idx0 / HW; hw0 = idx0 - a * HW;
                const float* fb = feat + ((size_t)(n * 255 + a * 85)) * HW + hw0;
                rx2 = *reinterpret_cast<const float2*>(fb);
                ry2 = *reinterpret_cast<const float2*>(fb + (size_t)HW);
                rw2 = *reinterpret_cast<const float2*>(fb + (size_t)2 * HW);
                rh2 = *reinterpret_cast<const float2*>(fb + (size_t)3 * HW);
                rc2 = *reinterpret_cast<const float2*>(fb + (size_t)4 * HW);
            }
        } else {
            const int idx = chunk * 256 + threadIdx.x;
            act = idx < C3;
            if (act) {
                idx0 = idx;
                a = idx / HW; hw0 = idx - a * HW;
                const float* fb = feat + ((size_t)(n * 255 + a * 85)) * HW + hw0;
                rx2.x = fb[0];
                ry2.x = fb[(size_t)HW];
                rw2.x = fb[(size_t)2 * HW];
                rh2.x = fb[(size_t)3 * HW];
                rc2.x = fb[(size_t)4 * HW];
            }
        }

        // ---- gather positives (consumes conf) ----
        bool wrote = false;
        #pragma unroll
        for (int k = 0; k < 2; k++) {
            if (cf[k] > 0.f) {                       // rare (~0.08%)
                wrote = true;
                const int c  = cbase + k * cstep;
                const int hw = c / 3;
                const int aa = c - hw * 3;
                const int key = aa * HW + hw;
                const float* p = label + (size_t)(n * C3 + c) * 85;
                const float x = __ldg(p + 0), y = __ldg(p + 1);
                const float w = __ldg(p + 2), h = __ldg(p + 3);
                const int slot = atomicAdd(&g_count[lev][n], 1);
                if (slot < MAXB) {
                    g_boxes[lev][n][slot] = make_float4(x - 0.5f * w, y - 0.5f * h,
                                                        x + 0.5f * w, y + 0.5f * h);
                    g_area[lev][n][slot] = w * h * (1.f / 3.f);
                    g_key [lev][n][slot] = key;
                }
                const int ps = atomicAdd(&g_pcount, 1);
                if (ps < PMAX)
                    g_plist[ps] = ((unsigned)lev << 17) | ((unsigned)n << 13) | (unsigned)key;
            }
        }
        // fence only warps that published boxes, then warp-granular arrival
        if (__any_sync(0xffffffffu, wrote)) __threadfence();
        __syncwarp();
        if (lane == 0) {
            atomicAdd(&g_grp[lev][n], 1u);
            atomicAdd(&g_gdone, 1u);
        }

        // ---- precompute corners + bce while the group completes ----
        float ax1 = 0.f, ay1 = 0.f, ax2 = 0.f, ay2 = 0.f, pa3a = 0.f, bn0 = 0.f;
        float bx1 = 0.f, by1 = 0.f, bx2 = 0.f, by2 = 0.f, pa3b = 0.f, bn1 = 0.f;
        const int nCell = vec ? 2 : 1;
        if (act) {
            const float gy  = (float)(hw0 / W);
            const float gx0 = (float)(hw0 - (hw0 / W) * W);
            const float stride = c_stride[lev];
            const float aw = c_anchor[lev][a][0];
            const float ah = c_anchor[lev][a][1];
            {
                const float ex = __expf(-rx2.x), ey = __expf(-ry2.x);
                const float d  = __fdividef(1.f, (1.f + ex) * (1.f + ey));
                const float px = ((1.f + ey) * d + gx0) * stride;
                const float py = ((1.f + ex) * d + gy)  * stride;
                const float pw = __expf(rw2.x) * aw, ph = __expf(rh2.x) * ah;
                ax1 = px - 0.5f * pw; ay1 = py - 0.5f * ph;
                ax2 = px + 0.5f * pw; ay2 = py + 0.5f * ph;
                pa3a = pw * ph * (1.f / 3.f);
                bn0 = bce0(rc2.x);
            }
            if (nCell == 2) {
                const float ex = __expf(-rx2.y), ey = __expf(-ry2.y);
                const float d  = __fdividef(1.f, (1.f + ex) * (1.f + ey));
                const float px = ((1.f + ey) * d + gx0 + 1.f) * stride;
                const float py = ((1.f + ex) * d + gy) * stride;
                const float pw = __expf(rw2.y) * aw, ph = __expf(rh2.y) * ah;
                bx1 = px - 0.5f * pw; by1 = py - 0.5f * ph;
                bx2 = px + 0.5f * pw; by2 = py + 0.5f * ph;
                pa3b = pw * ph * (1.f / 3.f);
                bn1 = bce0(rc2.y);
            }
        }

        // ---- spin for group completion (warp-granular target) ----
        if (threadIdx.x == 0) {
            const unsigned tgt = (unsigned)(gs * 8);
            volatile unsigned* p = &g_grp[lev][n];
            while (*p < tgt) { __nanosleep(32); }
            __threadfence();
        }
        __syncthreads();

        // ---- stage boxes ----
        __shared__ float4 s_box[MAXB];
        __shared__ float  s_ta3[MAXB];
        __shared__ int    s_key[MAXB];
        const int cnt = min(g_count[lev][n], MAXB);
        if (threadIdx.x < cnt) {
            s_box[threadIdx.x] = g_boxes[lev][n][threadIdx.x];
            s_ta3[threadIdx.x] = g_area[lev][n][threadIdx.x];
            s_key[threadIdx.x] = g_key[lev][n][threadIdx.x];
        }
        __syncthreads();

        // ---- conf loss: IoU/key loop + select ----
        if (act) {
            bool pos0 = false, pos1 = false, ign0 = true, ign1 = true;
            // iou >= 0.5  <=>  inter >= pa/3 + ta/3   (pa,ta > 0)
            #pragma unroll 2
            for (int k = 0; k < cnt; k++) {
                const float4 t = s_box[k];
                const float ta3 = s_ta3[k];
                const int   key = s_key[k];
                {
                    const float iw = fmaxf(fminf(ax2, t.z) - fmaxf(ax1, t.x), 0.f);
                    const float ih = fmaxf(fminf(ay2, t.w) - fmaxf(ay1, t.y), 0.f);
                    if (iw * ih >= pa3a + ta3) ign0 = false;
                    if (key == idx0) pos0 = true;
                }
                if (nCell == 2) {
                    const float iw = fmaxf(fminf(bx2, t.z) - fmaxf(bx1, t.x), 0.f);
                    const float ih = fmaxf(fminf(by2, t.w) - fmaxf(by1, t.y), 0.f);
                    if (iw * ih >= pa3b + ta3) ign1 = false;
                    if (key == idx0 + 1) pos1 = true;
                }
            }
            r_conf += pos0 ? (bn0 - rc2.x) : (ign0 ? bn0 : 0.f);
            if (nCell == 2)
                r_conf += pos1 ? (bn1 - rc2.y) : (ign1 ? bn1 : 0.f);
        }
    } else {
        // ================= positive path: warp-per-positive =================
        if (threadIdx.x == 0) {
            const unsigned tgt = (unsigned)(nMain * 8);
            volatile unsigned* p = &g_gdone;
            while (*p < tgt) { __nanosleep(64); }
            __threadfence();
        }
        __syncthreads();

        const int pcount = min(g_pcount, PMAX);
        const int gw = (b - nMain) * 8 + warp;
        for (int p = gw; p < pcount; p += PBLK * 8) {
            const unsigned pk = g_plist[p];
            const int lev = (int)(pk >> 17);
            const int n   = (int)((pk >> 13) & 15u);
            const int key = (int)(pk & 0x1FFFu);
            int H; const float* feat; const float* label;
            if (lev == 0)      { H = 52; feat = f0; label = lab0; }
            else if (lev == 1) { H = 26; feat = f1; label = lab1; }
            else               { H = 13; feat = f2; label = lab2; }
            const int W = H, HW = H * W;
            const int a  = key / HW;
            const int hw = key - a * HW;

            const float* fb = feat + ((size_t)(n * 255 + a * 85)) * HW + hw;
            const float* Lb = label + ((size_t)(n * HW + hw) * 3 + a) * 85;

            float fv = 0.f, lv = 0.f;
            if (lane < 4) {
                fv = fb[(size_t)lane * HW];
                lv = __ldg(Lb + lane);
            }
            const float rx = __shfl_sync(0xffffffffu, fv, 0);
            const float ry = __shfl_sync(0xffffffffu, fv, 1);
            const float rw = __shfl_sync(0xffffffffu, fv, 2);
            const float rh = __shfl_sync(0xffffffffu, fv, 3);
            const float lx = __shfl_sync(0xffffffffu, lv, 0);
            const float ly = __shfl_sync(0xffffffffu, lv, 1);
            const float lw = __shfl_sync(0xffffffffu, lv, 2);
            const float lh = __shfl_sync(0xffffffffu, lv, 3);

            float ps = 0.f;
            #pragma unroll
            for (int c0 = 0; c0 < NCLS; c0 += 32) {
                const int c = c0 + lane;
                if (c < NCLS) {
                    const float rp = fb[(size_t)(5 + c) * HW];
                    const float lp = __ldg(Lb + 5 + c);
                    ps += bce_logits(rp, lp);
                }
            }
            r_prob += ps;

            if (lane == 0) {
                const float gx = (float)(hw % W);
                const float gy = (float)(hw / W);
                const float stride = c_stride[lev];
                const float aw = c_anchor[lev][a][0];
                const float ah = c_anchor[lev][a][1];
                const float scale = 2.f - lw * lh * (1.f / (416.f * 416.f));
                const float inv_s = __fdividef(1.f, stride);
                const float ox = lx * inv_s - gx;
                const float oy = ly * inv_s - gy;
                const float xy = bce_logits(rx, ox) + bce_logits(ry, oy);
                const float wx = __logf(__fdividef(lw, aw) + 1e-7f);
                const float wy = __logf(__fdividef(lh, ah) + 1e-7f);
                const float dwx = rw - wx, dwy = rh - wy;
                r_reg += scale * (xy + 0.5f * (dwx * dwx + dwy * dwy));
            }
        }
    }

    // ---- block reduction + last-block finalize ----
    #pragma unroll
    for (int o = 16; o; o >>= 1) {
        r_reg  += __shfl_xor_sync(0xffffffffu, r_reg,  o);
        r_conf += __shfl_xor_sync(0xffffffffu, r_conf, o);
        r_prob += __shfl_xor_sync(0xffffffffu, r_prob, o);
    }
    __shared__ float s_r[8], s_c[8], s_p[8];
    if (lane == 0) { s_r[warp] = r_reg; s_c[warp] = r_conf; s_p[warp] = r_prob; }
    __syncthreads();

    if (threadIdx.x == 0) {
        float R = 0.f, C = 0.f, P = 0.f;
        #pragma unroll
        for (int w = 0; w < 8; w++) { R += s_r[w]; C += s_c[w]; P += s_p[w]; }
        atomicAdd(&g_acc[0], (double)R);
        atomicAdd(&g_acc[1], (double)C);
        atomicAdd(&g_acc[2], (double)P);

        __threadfence();
        const unsigned t = atomicAdd(&g_done, 1u);
        if (t == (unsigned)gridDim.x - 1u) {
            const double v0 = atomicAdd(&g_acc[0], 0.0);
            const double v1 = atomicAdd(&g_acc[1], 0.0);
            const double v2 = atomicAdd(&g_acc[2], 0.0);
            const double invN = 1.0 / (double)N;
            out[0] = (float)(v0 * invN);
            out[1] = (float)(v1 * invN);
            out[2] = (float)(v2 * invN);
            g_acc[0] = 0.0; g_acc[1] = 0.0; g_acc[2] = 0.0;
            #pragma unroll
            for (int l = 0; l < NLEV; l++)
                #pragma unroll
                for (int m = 0; m < NBMAX; m++) { g_count[l][m] = 0; g_grp[l][m] = 0u; }
            g_pcount = 0;
            g_gdone = 0u;
            g_done = 0u;
            __threadfence();
        }
    }
}

extern "C" void kernel_launch(void* const* d_in, const int* in_sizes, int n_in,
                              void* d_out, int out_size) {
    const float* f0 = (const float*)d_in[0];
    const float* f1 = (const float*)d_in[1];
    const float* f2 = (const float*)d_in[2];
    const float* l0 = (const float*)d_in[3];
    const float* l1 = (const float*)d_in[4];
    const float* l2 = (const float*)d_in[5];

    int N = in_sizes[0] / (255 * 52 * 52);
    if (N > NBMAX) N = NBMAX;

    k_yolo<<<N * LBPI + PBLK, 256>>>(f0, f1, f2, l0, l1, l2, N, (float*)d_out);
}

// round 14
// speedup vs baseline: 1.3200x; 1.1575x over previous
#include <cuda_runtime.h>
#include <math.h>

#define NLEV 3
#define NBMAX 16
#define MAXB 64
#define NCLS 80
#define PMAX 1024
// main loss blocks per image: lev0 pairs 4056 -> 16, lev1 pairs 1014 -> 4, lev2 scalar 507 -> 2
#define VB0 16
#define VB1 4
#define SB2 2
#define LBPI (VB0 + VB1 + SB2)   // 22 -> N=16 => 352 main blocks
#define PBLK 18                  // positive-path blocks

__constant__ float c_stride[NLEV] = {8.f, 16.f, 32.f};
__constant__ float c_anchor[NLEV][3][2] = {
    {{12.f, 16.f}, {19.f, 36.f}, {40.f, 28.f}},
    {{36.f, 75.f}, {76.f, 55.f}, {72.f, 146.f}},
    {{142.f, 110.f}, {192.f, 243.f}, {459.f, 401.f}}
};

// Persistent scratch; statically zero-initialized; finalize resets all.
__device__ float4   g_boxes[NLEV][NBMAX][MAXB];   // corners x1,y1,x2,y2
__device__ float    g_area [NLEV][NBMAX][MAXB];   // ta/3
__device__ int      g_key  [NLEV][NBMAX][MAXB];   // cell key = a*HW + hw
__device__ int      g_count[NLEV][NBMAX];
__device__ unsigned g_grp  [NLEV][NBMAX];         // BLOCK-granular arrival counters
__device__ unsigned g_plist[PMAX];                // packed (lev<<17 | n<<13 | key)
__device__ int      g_pcount;
__device__ unsigned g_gdone;                      // main BLOCKS done gathering
__device__ double   g_acc[3];
__device__ unsigned g_done;

__device__ __forceinline__ float bce0(float x) {  // bce(x,0); bce(x,1) = bce0(x) - x
    return fmaxf(x, 0.f) + __logf(1.f + __expf(-fabsf(x)));
}
__device__ __forceinline__ float bce_logits(float x, float t) {
    return fmaxf(x, 0.f) - x * t + __logf(1.f + __expf(-fabsf(x)));
}

__global__ void __launch_bounds__(256, 4)
k_yolo(const float* __restrict__ f0, const float* __restrict__ f1,
       const float* __restrict__ f2,
       const float* __restrict__ lab0, const float* __restrict__ lab1,
       const float* __restrict__ lab2,
       int N, float* __restrict__ out) {
    const int b = blockIdx.x;
    const int nMain = N * LBPI;
    const int warp = threadIdx.x >> 5, lane = threadIdx.x & 31;

    float r_reg = 0.f, r_conf = 0.f, r_prob = 0.f;

    if (b < nMain) {
        // ================= main block =================
        const int n = b / LBPI;
        const int r = b - n * LBPI;
        int lev, chunk, H, gs;
        const float* feat; const float* label;
        bool vec;
        if (r < VB0)            { lev = 0; chunk = r;             H = 52; feat = f0; label = lab0; gs = VB0; vec = true; }
        else if (r < VB0 + VB1) { lev = 1; chunk = r - VB0;       H = 26; feat = f1; label = lab1; gs = VB1; vec = true; }
        else                    { lev = 2; chunk = r - VB0 - VB1; H = 13; feat = f2; label = lab2; gs = SB2; vec = false; }
        const int W = H, HW = H * W;
        const int C3 = 3 * HW;

        // ---- issue gather conf loads + feature loads in one window ----
        const int K = vec ? 2 : 1;
        const int cbase = chunk * 256 + threadIdx.x;
        const int cstep = gs * 256;
        float cf[2];
        #pragma unroll
        for (int k = 0; k < 2; k++) {
            const int c = cbase + k * cstep;
            const bool v = (k < K) && (c < C3);
            cf[k] = v ? __ldcs(label + (size_t)(n * C3 + (v ? c : 0)) * 85 + 4) : 0.f;
        }

        int idx0 = 0, a = 0, hw0 = 0;
        float2 rx2 = {0.f,0.f}, ry2 = {0.f,0.f}, rw2 = {0.f,0.f},
               rh2 = {0.f,0.f}, rc2 = {0.f,0.f};
        bool act;
        if (vec) {
            const int pair = chunk * 256 + threadIdx.x;
            act = pair < (C3 >> 1);
            if (act) {
                idx0 = pair * 2;
                a = idx0 / HW; hw0 = idx0 - a * HW;
                const float* fb = feat + ((size_t)(n * 255 + a * 85)) * HW + hw0;
                rx2 = *reinterpret_cast<const float2*>(fb);
                ry2 = *reinterpret_cast<const float2*>(fb + (size_t)HW);
                rw2 = *reinterpret_cast<const float2*>(fb + (size_t)2 * HW);
                rh2 = *reinterpret_cast<const float2*>(fb + (size_t)3 * HW);
                rc2 = *reinterpret_cast<const float2*>(fb + (size_t)4 * HW);
            }
        } else {
            const int idx = chunk * 256 + threadIdx.x;
            act = idx < C3;
            if (act) {
                idx0 = idx;
                a = idx / HW; hw0 = idx - a * HW;
                const float* fb = feat + ((size_t)(n * 255 + a * 85)) * HW + hw0;
                rx2.x = fb[0];
                ry2.x = fb[(size_t)HW];
                rw2.x = fb[(size_t)2 * HW];
                rh2.x = fb[(size_t)3 * HW];
                rc2.x = fb[(size_t)4 * HW];
            }
        }

        // ---- gather positives (consumes conf) ----
        bool wrote = false;
        #pragma unroll
        for (int k = 0; k < 2; k++) {
            if (cf[k] > 0.f) {                       // rare (~0.08%)
                wrote = true;
                const int c  = cbase + k * cstep;
                const int hw = c / 3;
                const int aa = c - hw * 3;
                const int key = aa * HW + hw;
                const float* p = label + (size_t)(n * C3 + c) * 85;
                const float x = __ldg(p + 0), y = __ldg(p + 1);
                const float w = __ldg(p + 2), h = __ldg(p + 3);
                const int slot = atomicAdd(&g_count[lev][n], 1);
                if (slot < MAXB) {
                    g_boxes[lev][n][slot] = make_float4(x - 0.5f * w, y - 0.5f * h,
                                                        x + 0.5f * w, y + 0.5f * h);
                    g_area[lev][n][slot] = w * h * (1.f / 3.f);
                    g_key [lev][n][slot] = key;
                }
                const int ps = atomicAdd(&g_pcount, 1);
                if (ps < PMAX)
                    g_plist[ps] = ((unsigned)lev << 17) | ((unsigned)n << 13) | (unsigned)key;
            }
        }
        if (__syncthreads_or(wrote ? 1 : 0)) __threadfence();
        else __syncthreads();   // keep barrier counts identical on both paths
        // NOTE: __syncthreads_or already synchronizes; the else-branch extra
        // __syncthreads keeps arrival ordering safe on the non-writing path too.

        // ---- BLOCK-granular arrival (one atomic per block per counter) ----
        if (threadIdx.x == 0) {
            atomicAdd(&g_gdone, 1u);
            atomicAdd(&g_grp[lev][n], 1u);
        }

        // ---- hoisted compute while the group completes ----
        float ax1 = 0.f, ay1 = 0.f, ax2 = 0.f, ay2 = 0.f, pa3a = 0.f, bn0 = 0.f;
        float bx1 = 0.f, by1 = 0.f, bx2 = 0.f, by2 = 0.f, pa3b = 0.f, bn1 = 0.f;
        const int nCell = vec ? 2 : 1;
        if (act) {
            const float gy  = (float)(hw0 / W);
            const float gx0 = (float)(hw0 - (hw0 / W) * W);
            const float stride = c_stride[lev];
            const float aw = c_anchor[lev][a][0];
            const float ah = c_anchor[lev][a][1];
            {
                const float ex = __expf(-rx2.x), ey = __expf(-ry2.x);
                const float d  = __fdividef(1.f, (1.f + ex) * (1.f + ey));
                const float px = ((1.f + ey) * d + gx0) * stride;
                const float py = ((1.f + ex) * d + gy)  * stride;
                const float pw = __expf(rw2.x) * aw, ph = __expf(rh2.x) * ah;
                ax1 = px - 0.5f * pw; ay1 = py - 0.5f * ph;
                ax2 = px + 0.5f * pw; ay2 = py + 0.5f * ph;
                pa3a = pw * ph * (1.f / 3.f);
                bn0 = bce0(rc2.x);
            }
            if (nCell == 2) {
                const float ex = __expf(-rx2.y), ey = __expf(-ry2.y);
                const float d  = __fdividef(1.f, (1.f + ex) * (1.f + ey));
                const float px = ((1.f + ey) * d + gx0 + 1.f) * stride;
                const float py = ((1.f + ex) * d + gy) * stride;
                const float pw = __expf(rw2.y) * aw, ph = __expf(rh2.y) * ah;
                bx1 = px - 0.5f * pw; by1 = py - 0.5f * ph;
                bx2 = px + 0.5f * pw; by2 = py + 0.5f * ph;
                pa3b = pw * ph * (1.f / 3.f);
                bn1 = bce0(rc2.y);
            }
        }

        // ---- spin for group completion (block-granular target) ----
        if (threadIdx.x == 0) {
            volatile unsigned* p = &g_grp[lev][n];
            while (*p < (unsigned)gs) { __nanosleep(32); }
            __threadfence();
        }
        __syncthreads();

        // ---- stage boxes ----
        __shared__ float4 s_box[MAXB];
        __shared__ float  s_ta3[MAXB];
        __shared__ int    s_key[MAXB];
        const int cnt = min(g_count[lev][n], MAXB);
        if (threadIdx.x < cnt) {
            s_box[threadIdx.x] = g_boxes[lev][n][threadIdx.x];
            s_ta3[threadIdx.x] = g_area[lev][n][threadIdx.x];
            s_key[threadIdx.x] = g_key[lev][n][threadIdx.x];
        }
        __syncthreads();

        // ---- conf loss: IoU/key loop + select ----
        if (act) {
            bool pos0 = false, pos1 = false, ign0 = true, ign1 = true;
            // iou >= 0.5  <=>  inter >= pa/3 + ta/3   (pa,ta > 0)
            #pragma unroll 2
            for (int k = 0; k < cnt; k++) {
                const float4 t = s_box[k];
                const float ta3 = s_ta3[k];
                const int   key = s_key[k];
                {
                    const float iw = fmaxf(fminf(ax2, t.z) - fmaxf(ax1, t.x), 0.f);
                    const float ih = fmaxf(fminf(ay2, t.w) - fmaxf(ay1, t.y), 0.f);
                    if (iw * ih >= pa3a + ta3) ign0 = false;
                    if (key == idx0) pos0 = true;
                }
                if (nCell == 2) {
                    const float iw = fmaxf(fminf(bx2, t.z) - fmaxf(bx1, t.x), 0.f);
                    const float ih = fmaxf(fminf(by2, t.w) - fmaxf(by1, t.y), 0.f);
                    if (iw * ih >= pa3b + ta3) ign1 = false;
                    if (key == idx0 + 1) pos1 = true;
                }
            }
            r_conf += pos0 ? (bn0 - rc2.x) : (ign0 ? bn0 : 0.f);
            if (nCell == 2)
                r_conf += pos1 ? (bn1 - rc2.y) : (ign1 ? bn1 : 0.f);
        }
    } else {
        // ================= positive path: warp-per-positive =================
        if (threadIdx.x == 0) {
            volatile unsigned* p = &g_gdone;
            while (*p < (unsigned)nMain) { __nanosleep(64); }
            __threadfence();
        }
        __syncthreads();

        const int pcount = min(g_pcount, PMAX);
        const int gw = (b - nMain) * 8 + warp;
        for (int p = gw; p < pcount; p += PBLK * 8) {
            const unsigned pk = g_plist[p];
            const int lev = (int)(pk >> 17);
            const int n   = (int)((pk >> 13) & 15u);
            const int key = (int)(pk & 0x1FFFu);
            int H; const float* feat; const float* label;
            if (lev == 0)      { H = 52; feat = f0; label = lab0; }
            else if (lev == 1) { H = 26; feat = f1; label = lab1; }
            else               { H = 13; feat = f2; label = lab2; }
            const int W = H, HW = H * W;
            const int a  = key / HW;
            const int hw = key - a * HW;

            const float* fb = feat + ((size_t)(n * 255 + a * 85)) * HW + hw;
            const float* Lb = label + ((size_t)(n * HW + hw) * 3 + a) * 85;

            float fv = 0.f, lv = 0.f;
            if (lane < 4) {
                fv = fb[(size_t)lane * HW];
                lv = __ldg(Lb + lane);
            }
            const float rx = __shfl_sync(0xffffffffu, fv, 0);
            const float ry = __shfl_sync(0xffffffffu, fv, 1);
            const float rw = __shfl_sync(0xffffffffu, fv, 2);
            const float rh = __shfl_sync(0xffffffffu, fv, 3);
            const float lx = __shfl_sync(0xffffffffu, lv, 0);
            const float ly = __shfl_sync(0xffffffffu, lv, 1);
            const float lw = __shfl_sync(0xffffffffu, lv, 2);
            const float lh = __shfl_sync(0xffffffffu, lv, 3);

            float ps = 0.f;
            #pragma unroll
            for (int c0 = 0; c0 < NCLS; c0 += 32) {
                const int c = c0 + lane;
                if (c < NCLS) {
                    const float rp = fb[(size_t)(5 + c) * HW];
                    const float lp = __ldg(Lb + 5 + c);
                    ps += bce_logits(rp, lp);
                }
            }
            r_prob += ps;

            if (lane == 0) {
                const float gx = (float)(hw % W);
                const float gy = (float)(hw / W);
                const float stride = c_stride[lev];
                const float aw = c_anchor[lev][a][0];
                const float ah = c_anchor[lev][a][1];
                const float scale = 2.f - lw * lh * (1.f / (416.f * 416.f));
                const float inv_s = __fdividef(1.f, stride);
                const float ox = lx * inv_s - gx;
                const float oy = ly * inv_s - gy;
                const float xy = bce_logits(rx, ox) + bce_logits(ry, oy);
                const float wx = __logf(__fdividef(lw, aw) + 1e-7f);
                const float wy = __logf(__fdividef(lh, ah) + 1e-7f);
                const float dwx = rw - wx, dwy = rh - wy;
                r_reg += scale * (xy + 0.5f * (dwx * dwx + dwy * dwy));
            }
        }
    }

    // ---- block reduction + last-block finalize ----
    #pragma unroll
    for (int o = 16; o; o >>= 1) {
        r_reg  += __shfl_xor_sync(0xffffffffu, r_reg,  o);
        r_conf += __shfl_xor_sync(0xffffffffu, r_conf, o);
        r_prob += __shfl_xor_sync(0xffffffffu, r_prob, o);
    }
    __shared__ float s_r[8], s_c[8], s_p[8];
    if (lane == 0) { s_r[warp] = r_reg; s_c[warp] = r_conf; s_p[warp] = r_prob; }
    __syncthreads();

    if (threadIdx.x == 0) {
        float R = 0.f, C = 0.f, P = 0.f;
        #pragma unroll
        for (int w = 0; w < 8; w++) { R += s_r[w]; C += s_c[w]; P += s_p[w]; }
        atomicAdd(&g_acc[0], (double)R);
        atomicAdd(&g_acc[1], (double)C);
        atomicAdd(&g_acc[2], (double)P);

        __threadfence();
        const unsigned t = atomicAdd(&g_done, 1u);
        if (t == (unsigned)gridDim.x - 1u) {
            const double v0 = atomicAdd(&g_acc[0], 0.0);
            const double v1 = atomicAdd(&g_acc[1], 0.0);
            const double v2 = atomicAdd(&g_acc[2], 0.0);
            const double invN = 1.0 / (double)N;
            out[0] = (float)(v0 * invN);
            out[1] = (float)(v1 * invN);
            out[2] = (float)(v2 * invN);
            g_acc[0] = 0.0; g_acc[1] = 0.0; g_acc[2] = 0.0;
            #pragma unroll
            for (int l = 0; l < NLEV; l++)
                #pragma unroll
                for (int m = 0; m < NBMAX; m++) { g_count[l][m] = 0; g_grp[l][m] = 0u; }
            g_pcount = 0;
            g_gdone = 0u;
            g_done = 0u;
            __threadfence();
        }
    }
}

extern "C" void kernel_launch(void* const* d_in, const int* in_sizes, int n_in,
                              void* d_out, int out_size) {
    const float* f0 = (const float*)d_in[0];
    const float* f1 = (const float*)d_in[1];
    const float* f2 = (const float*)d_in[2];
    const float* l0 = (const float*)d_in[3];
    const float* l1 = (const float*)d_in[4];
    const float* l2 = (const float*)d_in[5];

    int N = in_sizes[0] / (255 * 52 * 52);
    if (N > NBMAX) N = NBMAX;

    k_yolo<<<N * LBPI + PBLK, 256>>>(f0, f1, f2, l0, l1, l2, N, (float*)d_out);
}